// round 2
// baseline (speedup 1.0000x reference)
#include <cuda_runtime.h>

#define BATCH 8
#define CH 3
#define H 1024
#define W 1280
#define HW (H * W)
#define EPS 1e-7f
#define MIN_DEPTH 10.0f
#define MAX_DEPTH 255.0f

// Per-batch fused parameters: M (9 floats, row-major 3x3) + c (3 floats)
__device__ float g_MC[BATCH * 12];

__global__ void setup_params_kernel(const float* __restrict__ srcK,
                                    const float* __restrict__ tgtK,
                                    const float* __restrict__ tvec) {
    int b = threadIdx.x;
    if (b >= BATCH) return;
    const float* S = srcK + b * 16;   // 4x4 row-major
    const float* T = tgtK + b * 16;
    const float* t = tvec + b * 3;

    float a00 = S[0], a01 = S[1], a02 = S[2];
    float a10 = S[4], a11 = S[5], a12 = S[6];
    float a20 = S[8], a21 = S[9], a22 = S[10];
    float det = a00 * (a11 * a22 - a12 * a21)
              - a01 * (a10 * a22 - a12 * a20)
              + a02 * (a10 * a21 - a11 * a20);
    float id = 1.0f / det;
    float i00 = (a11 * a22 - a12 * a21) * id;
    float i01 = (a02 * a21 - a01 * a22) * id;
    float i02 = (a01 * a12 - a02 * a11) * id;
    float i10 = (a12 * a20 - a10 * a22) * id;
    float i11 = (a00 * a22 - a02 * a20) * id;
    float i12 = (a02 * a10 - a00 * a12) * id;
    float i20 = (a10 * a21 - a11 * a20) * id;
    float i21 = (a01 * a20 - a00 * a21) * id;
    float i22 = (a00 * a11 - a01 * a10) * id;

    float k00 = T[0], k01 = T[1], k02 = T[2];
    float k10 = T[4], k11 = T[5], k12 = T[6];
    float k20 = T[8], k21 = T[9], k22 = T[10];

    float* P = g_MC + b * 12;
    P[0] = k00 * i00 + k01 * i10 + k02 * i20;
    P[1] = k00 * i01 + k01 * i11 + k02 * i21;
    P[2] = k00 * i02 + k01 * i12 + k02 * i22;
    P[3] = k10 * i00 + k11 * i10 + k12 * i20;
    P[4] = k10 * i01 + k11 * i11 + k12 * i21;
    P[5] = k10 * i02 + k11 * i12 + k12 * i22;
    P[6] = k20 * i00 + k21 * i10 + k22 * i20;
    P[7] = k20 * i01 + k21 * i11 + k22 * i21;
    P[8] = k20 * i02 + k21 * i12 + k22 * i22;
    P[9]  = k00 * t[0] + k01 * t[1] + k02 * t[2];
    P[10] = k10 * t[0] + k11 * t[1] + k12 * t[2];
    P[11] = k20 * t[0] + k21 * t[1] + k22 * t[2];
}

// grid: (W/4/64, H, BATCH), block: 64 threads, 4 pixels (along x) per thread.
__global__ __launch_bounds__(64) void synth_kernel(const float* __restrict__ img,
                                                   const float* __restrict__ disp,
                                                   float* __restrict__ out) {
    const int b = blockIdx.z;
    const int y = blockIdx.y;
    const int x0base = (blockIdx.x * 64 + threadIdx.x) * 4;

    __shared__ float sP[12];
    if (threadIdx.x < 12) sP[threadIdx.x] = g_MC[b * 12 + threadIdx.x];
    __syncthreads();

    const float m0 = sP[0], m1 = sP[1], m2 = sP[2];
    const float m3 = sP[3], m4 = sP[4], m5 = sP[5];
    const float m6 = sP[6], m7 = sP[7], m8 = sP[8];
    const float c0 = sP[9], c1 = sP[10], c2 = sP[11];

    const size_t bimg = (size_t)b * CH * HW;
    const int rowoff = y * W + x0base;

    // disp -> depth, vectorized load
    const float4 d4 = *(const float4*)(disp + (size_t)b * HW + rowoff);

    const float min_disp = 1.0f / MAX_DEPTH;
    const float max_disp = 1.0f / MIN_DEPTH;

    float4 r0, r1, r2;   // accumulators per channel
    float* acc0 = (float*)&r0;
    float* acc1 = (float*)&r1;
    float* acc2 = (float*)&r2;
    const float* dv = (const float*)&d4;

    const float fy = (float)y;
    // y-dependent part of the projection (uniform across the quad)
    const float py_x = m1 * fy + m2;
    const float py_y = m4 * fy + m5;
    const float py_z = m7 * fy + m8;

    const float* imb = img + bimg;

#pragma unroll
    for (int i = 0; i < 4; i++) {
        float depth = 1.0f / (min_disp + (max_disp - min_disp) * dv[i]);
        float fx = (float)(x0base + i);
        float cpx = depth * (m0 * fx + py_x) + c0;
        float cpy = depth * (m3 * fx + py_y) + c1;
        float cpz = depth * (m6 * fx + py_z) + c2;

        float inv_z = 1.0f / (cpz + EPS);
        float pcx = cpx * inv_z;
        float pcy = cpy * inv_z;

        float gx = (pcx * (1.0f / (float)(W - 1)) - 0.5f) * 2.0f;
        float gy = (pcy * (1.0f / (float)(H - 1)) - 0.5f) * 2.0f;
        float xf = (gx + 1.0f) * (float)W * 0.5f - 0.5f;
        float yf = (gy + 1.0f) * (float)H * 0.5f - 0.5f;

        float x0f = floorf(xf);
        float y0f = floorf(yf);
        float wx = xf - x0f;
        float wy = yf - y0f;

        int ix0 = (int)x0f;
        int iy0 = (int)y0f;
        int ix1 = min(max(ix0 + 1, 0), W - 1);
        int iy1 = min(max(iy0 + 1, 0), H - 1);
        ix0 = min(max(ix0, 0), W - 1);
        iy0 = min(max(iy0, 0), H - 1);

        float w00 = (1.0f - wx) * (1.0f - wy);
        float w01 = wx * (1.0f - wy);
        float w10 = (1.0f - wx) * wy;
        float w11 = wx * wy;

        int o00 = iy0 * W + ix0;
        int o01 = iy0 * W + ix1;
        int o10 = iy1 * W + ix0;
        int o11 = iy1 * W + ix1;

        {
            const float* p = imb;
            acc0[i] = __ldg(p + o00) * w00 + __ldg(p + o01) * w01
                    + __ldg(p + o10) * w10 + __ldg(p + o11) * w11;
        }
        {
            const float* p = imb + HW;
            acc1[i] = __ldg(p + o00) * w00 + __ldg(p + o01) * w01
                    + __ldg(p + o10) * w10 + __ldg(p + o11) * w11;
        }
        {
            const float* p = imb + 2 * HW;
            acc2[i] = __ldg(p + o00) * w00 + __ldg(p + o01) * w01
                    + __ldg(p + o10) * w10 + __ldg(p + o11) * w11;
        }
    }

    float* outb = out + bimg;
    *(float4*)(outb + rowoff)            = r0;
    *(float4*)(outb + HW + rowoff)       = r1;
    *(float4*)(outb + 2 * HW + rowoff)   = r2;
}

extern "C" void kernel_launch(void* const* d_in, const int* in_sizes, int n_in,
                              void* d_out, int out_size) {
    const float* img  = (const float*)d_in[0];
    const float* disp = (const float*)d_in[1];
    const float* srcK = (const float*)d_in[2];
    const float* tgtK = (const float*)d_in[3];
    const float* tvec = (const float*)d_in[4];
    float* out = (float*)d_out;

    setup_params_kernel<<<1, BATCH>>>(srcK, tgtK, tvec);
    dim3 grid(W / 4 / 64, H, BATCH);   // (5, 1024, 8)
    synth_kernel<<<grid, 64>>>(img, disp, out);
}